// round 16
// baseline (speedup 1.0000x reference)
#include <cuda_runtime.h>
#include <cuda_fp16.h>
#include <math.h>

#define NT 128
#define NAA 21
#define FR_U32 (48 * NT)      // 8 frames * 12 comps as 48 half2 per thread, [pair][tid]
#define DF_STRIDE_H 49        // odd (half2 units) -> conflict-free across random aa
#define DF_U32 (NAA * DF_STRIDE_H)          // 1029 u32
#define AT_WORDS (NAA * 10)                 // per array: [10 atoms][21 aa]
#define SMEM_FLOATS (FR_U32 + DF_U32 + 3 * AT_WORDS)   // 6144+1029+630 = 7803 fl = 31212 B -> 7 blocks/SM

struct V3 { float x, y, z; };

__device__ __forceinline__ V3 vsub(V3 a, V3 b) { return V3{a.x - b.x, a.y - b.y, a.z - b.z}; }
__device__ __forceinline__ V3 vcross(V3 a, V3 b) {
    return V3{a.y * b.z - a.z * b.y, a.z * b.x - a.x * b.z, a.x * b.y - a.y * b.x};
}
__device__ __forceinline__ float vdot(V3 a, V3 b) { return a.x * b.x + a.y * b.y + a.z * b.z; }

// fast atan2: minimax poly on [0,1] + quadrant fixes. |err| ~1e-6 rad << 1e-3 budget.
// (0,0) -> NaN -> folded to 0 by caller (reference arctan2(0,0)=0 too).
__device__ __forceinline__ float fast_atan2f(float y, float x) {
    float ax = fabsf(x), ay = fabsf(y);
    float mx = fmaxf(ax, ay), mn = fminf(ax, ay);
    float t = __fdividef(mn, mx);
    float t2 = t * t;
    float p = -0.0117212f;
    p = fmaf(p, t2,  0.05265332f);
    p = fmaf(p, t2, -0.11643287f);
    p = fmaf(p, t2,  0.19354346f);
    p = fmaf(p, t2, -0.33262347f);
    p = fmaf(p, t2,  0.99997726f);
    float r = p * t;
    r = (ay > ax) ? (1.5707963267948966f - r) : r;
    r = (x < 0.0f) ? (3.14159265358979323846f - r) : r;
    return copysignf(r, y);
}

__device__ __forceinline__ float dihedral(V3 p0, V3 p1, V3 p2, V3 p3) {
    V3 b0 = vsub(p0, p1);
    V3 b1 = vsub(p2, p1);
    V3 b2 = vsub(p3, p2);
    V3 v1 = vcross(b0, b1);
    V3 v2 = vcross(b2, b1);
    float y = vdot(vcross(v1, v2), b1) * rsqrtf(vdot(b1, b1));
    float x = vdot(v1, v2);
    float a = fast_atan2f(y, x);
    return (a != a) ? 0.0f : a;
}

__global__ void __launch_bounds__(NT, 7)
idealizer_kernel(const int* __restrict__ aa,
                 const float* __restrict__ bb,      // [n,4,3]
                 const float* __restrict__ tor,     // [n,4]
                 const float* __restrict__ dfr,     // [21,8,4,4]
                 const int* __restrict__ gidx,      // [21,14]
                 const float* __restrict__ amask,   // [21,14]
                 const float* __restrict__ lit,     // [21,14,3]
                 float* __restrict__ out,           // [n,14,3]
                 int n)
{
    extern __shared__ float smem[];
    __half2* fr_h = reinterpret_cast<__half2*>(smem);   // [48 pairs][NT] fp16 frames
    float2*  st2b = reinterpret_cast<float2*>(smem);    // bb staging view (pairs 0..5, fp32)
    __half2* df_h = reinterpret_cast<__half2*>(smem + FR_U32);  // [21][49] half2, odd stride
    int*     atg_s = reinterpret_cast<int*>(smem + FR_U32 + DF_U32);      // [10][21]: g
    __half2* atl0  = reinterpret_cast<__half2*>(smem + FR_U32 + DF_U32 + AT_WORDS);      // (lx,ly)
    __half2* atl1  = reinterpret_cast<__half2*>(smem + FR_U32 + DF_U32 + 2 * AT_WORDS);  // (lz,m)

    const int tid = threadIdx.x;
    const int base = blockIdx.x * NT;
    const int i = base + tid;
    const bool active = i < n;

    float bbv[12];
    float t4x, t4y, t4z, t4w;
    int a_i = 0;

    if (active) {
        const float4* b4 = reinterpret_cast<const float4*>(bb) + (size_t)i * 3;
        float4 q0 = b4[0], q1 = b4[1], q2 = b4[2];
        bbv[0] = q0.x; bbv[1] = q0.y; bbv[2]  = q0.z; bbv[3]  = q0.w;
        bbv[4] = q1.x; bbv[5] = q1.y; bbv[6]  = q1.z; bbv[7]  = q1.w;
        bbv[8] = q2.x; bbv[9] = q2.y; bbv[10] = q2.z; bbv[11] = q2.w;
        const float4 t4 = reinterpret_cast<const float4*>(tor)[i];
        t4x = t4.x; t4y = t4.y; t4z = t4.z; t4w = t4.w;
        a_i = aa[i];
        // stage bb (fp32) for neighbor dihedral reads; conflict-free STS.64
        #pragma unroll
        for (int p = 0; p < 6; p++)
            st2b[p * NT + tid] = make_float2(bbv[2 * p], bbv[2 * p + 1]);
    }

    // ---- cooperative table loads (one div, 21 unrolled iterations) ----
    // df as half2: word w = k*6+p holds floats (k*12+2p, k*12+2p+1); dst stride 49 (odd)
    {
        int kk = tid / 6;
        int pp = tid - kk * 6;
        if (tid < 48) {
            const float* src = dfr + kk * 16 + 2 * pp;
            __half2* dst = df_h + tid;
            #pragma unroll
            for (int a = 0; a < NAA; a++)
                dst[a * DF_STRIDE_H] = __floats2half2_rn(__ldg(src + a * 128),
                                                         __ldg(src + a * 128 + 1));
        }
    }
    // atoms: 210 records x 3 words, [atom][aa] layout (read side: lanes differ in aa)
    for (int idx = tid; idx < NAA * 10; idx += NT) {
        int at = idx / NAA;
        int a  = idx - at * NAA;
        int ai = a * 14 + at + 4;
        atg_s[idx] = __ldg(gidx + ai);
        atl0[idx]  = __floats2half2_rn(__ldg(lit + (size_t)ai * 3 + 0),
                                       __ldg(lit + (size_t)ai * 3 + 1));
        atl1[idx]  = __floats2half2_rn(__ldg(lit + (size_t)ai * 3 + 2),
                                       __ldg(amask + ai));   // mask is exactly 0.0 or 1.0
    }
    __syncthreads();

    float ang[7];
    float M00, M01, M02, M10, M11, M12, M20, M21, M22;
    V3 CAv;

    if (active) {
        V3 Nv  = {bbv[0], bbv[1], bbv[2]};
        CAv    = {bbv[3], bbv[4], bbv[5]};
        V3 Cv  = {bbv[6], bbv[7], bbv[8]};

        // ---- dihedrals: [omega, phi, psi, sc0..3]; omega & psi share a cross product ----
        if (i + 1 < n) {
            V3 Nn, CAn;
            if (tid < NT - 1) {
                float2 p0 = st2b[0 * NT + tid + 1];
                float2 p1 = st2b[1 * NT + tid + 1];
                float2 p2 = st2b[2 * NT + tid + 1];
                Nn  = {p0.x, p0.y, p1.x};
                CAn = {p1.y, p2.x, p2.y};
            } else {
                const float* nb = bb + (size_t)(i + 1) * 12;
                Nn  = {nb[0], nb[1], nb[2]};
                CAn = {nb[3], nb[4], nb[5]};
            }
            V3 e1  = vsub(Nn, Cv);          // omega.b1 = psi's (Nn - C)
            V3 b0o = vsub(CAv, Cv);
            V3 b2o = vsub(CAn, Nn);
            V3 v1o = vcross(b0o, e1);       // == psi.v2 exactly
            V3 v2o = vcross(b2o, e1);
            float yo = vdot(vcross(v1o, v2o), e1) * rsqrtf(vdot(e1, e1));
            float xo = vdot(v1o, v2o);
            float ao = fast_atan2f(yo, xo);
            ang[0] = (ao != ao) ? 0.0f : ao;
            V3 b0p = vsub(Nv, CAv);
            V3 b1p = vsub(Cv, CAv);
            V3 v1p = vcross(b0p, b1p);
            float yp = vdot(vcross(v1p, v1o), b1p) * rsqrtf(vdot(b1p, b1p));
            float xp = vdot(v1p, v1o);
            float ap = fast_atan2f(yp, xp);
            ang[2] = (ap != ap) ? 0.0f : ap;
        } else { ang[0] = 0.f; ang[2] = 0.f; }
        if (i > 0) {
            V3 Cp;
            if (tid > 0) {
                float2 p3 = st2b[3 * NT + tid - 1];
                float2 p4 = st2b[4 * NT + tid - 1];
                Cp = {p3.x, p3.y, p4.x};
            } else {
                const float* pb = bb + (size_t)(i - 1) * 12;
                Cp = {pb[6], pb[7], pb[8]};
            }
            ang[1] = dihedral(Cp, Nv, CAv, Cv);    // phi
        } else { ang[1] = 0.f; }
        ang[3] = t4x; ang[4] = t4y; ang[5] = t4z; ang[6] = t4w;

        // ---- backbone frame ----
        V3 nrel = vsub(Nv, CAv);
        V3 crel = vsub(Cv, CAv);
        const float eps = 1e-20f;
        float txy = crel.x * crel.x + crel.y * crel.y;
        float i1 = rsqrtf(eps + txy);
        float s1 = -crel.y * i1, c1 = crel.x * i1;
        float i2 = rsqrtf(eps + txy + crel.z * crel.z);
        float s2 = crel.z * i2, c2 = sqrtf(txy) * i2;
        float Rc00 =  c2 * c1, Rc01 = -c2 * s1, Rc02 = s2;
        float Rc10 =  s1,      Rc11 =  c1;
        float Rc20 = -s2 * c1, Rc21 =  s2 * s1, Rc22 = c2;
        float n2y = Rc10 * nrel.x + Rc11 * nrel.y;
        float n2z = Rc20 * nrel.x + Rc21 * nrel.y + Rc22 * nrel.z;
        float i3 = rsqrtf(eps + n2y * n2y + n2z * n2z);
        float sn = -n2z * i3, cn = n2y * i3;
        M00 = Rc00; M01 = Rc01; M02 = Rc02;
        M10 = cn * Rc10 - sn * Rc20;
        M11 = cn * Rc11 - sn * Rc21;
        M12 = -sn * Rc22;
        M20 = sn * Rc10 + cn * Rc20;
        M21 = sn * Rc11 + cn * Rc21;
        M22 = cn * Rc22;
    }

    __syncthreads();   // neighbor bb reads done; frames may overwrite staging

    float pred[30];
    if (active) {
        const __half2* dfa = df_h + a_i * DF_STRIDE_H;
        float rr[9], rt[3];

        #pragma unroll
        for (int k = 0; k < 8; k++) {
            // 6 scalar half2 loads (odd stride -> conflict-free), widen to fp32
            float2 e0 = __half22float2(dfa[k * 6 + 0]);   // r00 r01
            float2 e1 = __half22float2(dfa[k * 6 + 1]);   // r02 t0
            float2 e2 = __half22float2(dfa[k * 6 + 2]);   // r10 r11
            float2 e3 = __half22float2(dfa[k * 6 + 3]);   // r12 t1
            float2 e4 = __half22float2(dfa[k * 6 + 4]);   // r20 r21
            float2 e5 = __half22float2(dfa[k * 6 + 5]);   // r22 t2
            float s, c;
            if (k == 0) { s = 0.f; c = 1.f; }
            else { __sincosf(ang[k - 1], &s, &c); }
            float f00 = e0.x, f01 = c * e0.y + s * e1.x,  f02 = -s * e0.y + c * e1.x;
            float f10 = e2.x, f11 = c * e2.y + s * e3.x,  f12 = -s * e2.y + c * e3.x;
            float f20 = e4.x, f21 = c * e4.y + s * e5.x,  f22 = -s * e4.y + c * e5.x;
            float ft0 = e1.y, ft1 = e3.y, ft2 = e5.y;

            float c00, c01, c02, c10, c11, c12, c20, c21, c22, ct0, ct1, ct2;
            if (k <= 4) {
                c00 = f00; c01 = f01; c02 = f02;
                c10 = f10; c11 = f11; c12 = f12;
                c20 = f20; c21 = f21; c22 = f22;
                ct0 = ft0; ct1 = ft1; ct2 = ft2;
                if (k == 4) {
                    rr[0]=f00; rr[1]=f01; rr[2]=f02; rr[3]=f10; rr[4]=f11; rr[5]=f12;
                    rr[6]=f20; rr[7]=f21; rr[8]=f22; rt[0]=ft0; rt[1]=ft1; rt[2]=ft2;
                }
            } else {
                float n00 = rr[0]*f00 + rr[1]*f10 + rr[2]*f20;
                float n01 = rr[0]*f01 + rr[1]*f11 + rr[2]*f21;
                float n02 = rr[0]*f02 + rr[1]*f12 + rr[2]*f22;
                float n10 = rr[3]*f00 + rr[4]*f10 + rr[5]*f20;
                float n11 = rr[3]*f01 + rr[4]*f11 + rr[5]*f21;
                float n12 = rr[3]*f02 + rr[4]*f12 + rr[5]*f22;
                float n20 = rr[6]*f00 + rr[7]*f10 + rr[8]*f20;
                float n21 = rr[6]*f01 + rr[7]*f11 + rr[8]*f21;
                float n22 = rr[6]*f02 + rr[7]*f12 + rr[8]*f22;
                float nt0 = rr[0]*ft0 + rr[1]*ft1 + rr[2]*ft2 + rt[0];
                float nt1 = rr[3]*ft0 + rr[4]*ft1 + rr[5]*ft2 + rt[1];
                float nt2 = rr[6]*ft0 + rr[7]*ft1 + rr[8]*ft2 + rt[2];
                rr[0]=n00; rr[1]=n01; rr[2]=n02; rr[3]=n10; rr[4]=n11; rr[5]=n12;
                rr[6]=n20; rr[7]=n21; rr[8]=n22; rt[0]=nt0; rt[1]=nt1; rt[2]=nt2;
                c00=n00; c01=n01; c02=n02; c10=n10; c11=n11; c12=n12;
                c20=n20; c21=n21; c22=n22; ct0=nt0; ct1=nt1; ct2=nt2;
            }
            // store LOCAL composed frame as 6 half2 pairs (conflict-free STS.32)
            int kp = k * 6;
            fr_h[(kp + 0) * NT + tid] = __floats2half2_rn(c00, c01);
            fr_h[(kp + 1) * NT + tid] = __floats2half2_rn(c02, c10);
            fr_h[(kp + 2) * NT + tid] = __floats2half2_rn(c11, c12);
            fr_h[(kp + 3) * NT + tid] = __floats2half2_rn(c20, c21);
            fr_h[(kp + 4) * NT + tid] = __floats2half2_rn(c22, ct0);
            fr_h[(kp + 5) * NT + tid] = __floats2half2_rn(ct1, ct2);
        }

        // ---- atoms 4..13: 3 table LDS/atom + conflict-free half2 frame gather ----
        #pragma unroll
        for (int a = 0; a < 10; a++) {
            int rec = a * NAA + a_i;
            int g = atg_s[rec];                       // raw int, no decode
            float2 lxy = __half22float2(atl0[rec]);
            float2 lzm = __half22float2(atl1[rec]);
            float lx = lxy.x, ly = lxy.y, lz = lzm.x, m = lzm.y;
            int gp = g * 6;
            // bank = tid mod 32 regardless of gp -> conflict-free
            float2 p0 = __half22float2(fr_h[(gp + 0) * NT + tid]);
            float2 p1 = __half22float2(fr_h[(gp + 1) * NT + tid]);
            float2 p2 = __half22float2(fr_h[(gp + 2) * NT + tid]);
            float2 p3 = __half22float2(fr_h[(gp + 3) * NT + tid]);
            float2 p4 = __half22float2(fr_h[(gp + 4) * NT + tid]);
            float2 p5 = __half22float2(fr_h[(gp + 5) * NT + tid]);
            float vx = p0.x * lx + p0.y * ly + p1.x * lz + p4.y;
            float vy = p1.y * lx + p2.x * ly + p2.y * lz + p5.x;
            float vz = p3.x * lx + p3.y * ly + p4.x * lz + p5.y;
            pred[a * 3 + 0] = (M00 * vx + M10 * vy + M20 * vz + CAv.x) * m;
            pred[a * 3 + 1] = (M01 * vx + M11 * vy + M21 * vz + CAv.y) * m;
            pred[a * 3 + 2] = (M02 * vx + M12 * vy + M22 * vz + CAv.z) * m;
        }
    }

    // ---- output: stage linear image at stride 42 (float2, conflict-free), float4 copy out ----
    __syncthreads();   // all frame reads done; reuse FR region as staging (42*NT <= 48*NT)
    if (active) {
        float2* st2 = reinterpret_cast<float2*>(smem + tid * 42);
        #pragma unroll
        for (int j = 0; j < 6; j++) st2[j] = make_float2(bbv[2 * j], bbv[2 * j + 1]);
        #pragma unroll
        for (int j = 0; j < 15; j++) st2[6 + j] = make_float2(pred[2 * j], pred[2 * j + 1]);
    }
    __syncthreads();

    int nvalid = n - base; if (nvalid > NT) nvalid = NT;
    int total = nvalid * 42;
    float* gout = out + (size_t)base * 42;
    int total4 = total >> 2;
    const float4* s4 = reinterpret_cast<const float4*>(smem);
    float4* g4 = reinterpret_cast<float4*>(gout);
    for (int idx = tid; idx < total4; idx += NT) g4[idx] = s4[idx];
    for (int idx = (total4 << 2) + tid; idx < total; idx += NT) gout[idx] = smem[idx];
}

extern "C" void kernel_launch(void* const* d_in, const int* in_sizes, int n_in,
                              void* d_out, int out_size) {
    const int*   aa    = (const int*)d_in[0];
    const float* bb    = (const float*)d_in[1];
    const float* tor   = (const float*)d_in[2];
    const float* dfr   = (const float*)d_in[3];
    const int*   gidx  = (const int*)d_in[4];
    const float* amask = (const float*)d_in[5];
    const float* lit   = (const float*)d_in[6];
    float* out = (float*)d_out;

    int n = in_sizes[0];
    int grid = (n + NT - 1) / NT;
    size_t smem_bytes = (size_t)SMEM_FLOATS * sizeof(float);   // 31212 B -> 7 blocks/SM
    cudaFuncSetAttribute(idealizer_kernel, cudaFuncAttributeMaxDynamicSharedMemorySize,
                         (int)smem_bytes);
    idealizer_kernel<<<grid, NT, smem_bytes>>>(aa, bb, tor, dfr, gidx, amask, lit, out, n);
}